// round 16
// baseline (speedup 1.0000x reference)
#include <cuda_runtime.h>

// DirichletLoss: ball query (r=0.15, K=32 nearest within radius) + neighbor
// feature variance, mean over all B*N queries, *0.5.
//
// 2-kernel pipeline (graph-capturable, scratch in __device__ globals):
//   k_build : per-batch block — smem histogram over anisotropic grid
//             7(z) x 7(y) x 32(x), hierarchical smem scan (2 cells/thread),
//             counting-sort into float4(x,y,z,f) cell-major; global offsets
//   k_main  : warp-per-query, TWO cheap passes (no top-K list in the hot
//             loop):
//             Pass 1: 16-bucket d2 histogram in packed per-lane registers
//                     (two u64, 8 buckets x 8 bits) -> warp reduce ->
//                     threshold bucket B* holding the 32nd smallest.
//             Pass 2: rescan with radius sqrt(t_hi) (tighter window):
//                     bucket<B* accumulates (f_i-f_j)^2 branch-free;
//                     bucket==B* members (few) go through a small sorted
//                     insert; first `need` of them contribute.
//             Block partial -> last-block deterministic reduction -> out.
//
// All candidate ranges are clamped so every loop terminates even if the
// offset table were corrupt (bugs become wrong answers, not hangs).

#define FULLMASK 0xFFFFFFFFu

constexpr int   B    = 8;
constexpr int   N    = 4096;
constexpr int   BN   = B * N;
constexpr int   GDY  = 7;               // y,z cells (size 0.15 = r)
constexpr int   GDX  = 32;              // fine x cells (size 1/32)
constexpr int   NC   = GDY * GDY * GDX; // 1568 cells per batch
constexpr int   TOTC = B * NC;
constexpr int   NBLK = BN / 8;          // k_main blocks (8 warps each)
constexpr float R        = 0.15f;
constexpr float R2       = 0.15f * 0.15f;
constexpr float CELLYZ   = 0.15f;
constexpr float INV_YZ   = 1.0f / 0.15f;
constexpr float CSCALE   = 16.0f / R2;  // d2 -> bucket scale
constexpr float BIGF     = 3.0e38f;
constexpr unsigned SENT  = 0xFFFFFFFFu;

__device__ int      g_off[TOTC + 1];
__device__ float4   g_pts[BN];          // (x,y,z,f) sorted by global cell id
__device__ float    g_var[NBLK];        // per-block partial sums
__device__ unsigned g_done;             // last-block ticket

__device__ __forceinline__ int cellyz(float v) {
    int c = (int)(v * INV_YZ);
    c = c < 0 ? 0 : c;
    return c > GDY - 1 ? GDY - 1 : c;
}
__device__ __forceinline__ int cellx(float v) {
    int c = (int)(v * (float)GDX);
    c = c < 0 ? 0 : c;
    return c > GDX - 1 ? GDX - 1 : c;
}

// One block per batch: smem histogram -> hierarchical scan -> scatter.
__global__ void __launch_bounds__(1024) k_build(const float* __restrict__ pos,
                                                const float* __restrict__ f) {
    __shared__ int cnt[NC];
    __shared__ int cur[NC];             // fill cursors (exclusive offsets)
    __shared__ int wt[32], wb[32];
    int b = blockIdx.x, t = threadIdx.x;
    int lane = t & 31, w = t >> 5;
    int base = b * N;

    if (b == 0 && t == 0) g_done = 0;   // reset reduction ticket
    for (int i = t; i < NC; i += 1024) cnt[i] = 0;
    __syncthreads();

    float mx[4], my[4], mz[4], mf[4];
    int   mc[4];
    #pragma unroll
    for (int k = 0; k < 4; k++) {
        int gi = base + t + k * 1024;
        float x = pos[3 * gi], y = pos[3 * gi + 1], z = pos[3 * gi + 2];
        mx[k] = x; my[k] = y; mz[k] = z; mf[k] = f[gi];
        int c = (cellyz(z) * GDY + cellyz(y)) * GDX + cellx(x);
        mc[k] = c;
        atomicAdd(&cnt[c], 1);
    }
    __syncthreads();

    // Exclusive scan over NC=1568 smem counts: 2 cells/thread.
    int i0 = 2 * t, i1 = 2 * t + 1;
    int c0 = (i0 < NC) ? cnt[i0] : 0;
    int c1 = (i1 < NC) ? cnt[i1] : 0;
    int s  = c0 + c1;
    int v  = s;
    #pragma unroll
    for (int d = 1; d < 32; d <<= 1) {
        int u = __shfl_up_sync(FULLMASK, v, d);
        if (lane >= d) v += u;
    }
    if (lane == 31) wt[w] = v;
    __syncthreads();
    if (w == 0) {
        int x = wt[lane];
        int vv = x;
        #pragma unroll
        for (int d = 1; d < 32; d <<= 1) {
            int u = __shfl_up_sync(FULLMASK, vv, d);
            if (lane >= d) vv += u;
        }
        wb[lane] = vv - x;              // exclusive warp base
    }
    __syncthreads();
    int run = wb[w] + v - s;            // thread's exclusive start
    if (i0 < NC) { cur[i0] = run; g_off[b * NC + i0] = base + run; run += c0; }
    if (i1 < NC) { cur[i1] = run; g_off[b * NC + i1] = base + run; }
    if (b == B - 1 && t == 1023) g_off[TOTC] = BN;
    __syncthreads();

    #pragma unroll
    for (int k = 0; k < 4; k++) {
        int dst = base + atomicAdd(&cur[mc[k]], 1);
        if (dst >= 0 && dst < BN)
            g_pts[dst] = make_float4(mx[k], my[k], mz[k], mf[k]);
    }
}

// One warp per query; histogram-select; last block reduces.
__global__ void __launch_bounds__(256) k_main(float* __restrict__ out) {
    __shared__ float  swarp[8];
    __shared__ double sd[256];
    __shared__ bool   amLast;
    int lane = threadIdx.x & 31;
    int wid  = threadIdx.x >> 5;
    int q    = blockIdx.x * 8 + wid;

    float4 p = g_pts[q];
    int b    = q >> 12;                 // build is batch-major -> contiguous
    int base = b * N;
    const float4* pbase = g_pts + base;
    int cy = cellyz(p.y), cz = cellyz(p.z);
    int xl = cellx(p.x - R), xh = cellx(p.x + R);   // pass-1 x window

    // Lane-parallel prologue: lanes 0..8 own the 9 stencil rows.
    int   rb = -1;                      // row base cell index (-1 invalid)
    float rm2f = BIGF;                  // row min distance^2 (y,z slabs)
    int rs0 = 0, rs1 = 0;               // pass-1 candidate range
    {
        const signed char DZ[9] = {0, 0, 0, -1, -1, -1, 1, 1, 1};
        const signed char DY[9] = {0, -1, 1, 0, -1, 1, 0, -1, 1};
        if (lane < 9) {
            int z = cz + DZ[lane], y = cy + DY[lane];
            if (z >= 0 && z < GDY && y >= 0 && y < GDY) {
                rb = b * NC + (z * GDY + y) * GDX;
                int a0 = g_off[rb + xl] - base;
                int a1 = g_off[rb + xh + 1] - base;
                a0 = a0 < 0 ? 0 : a0;               // termination guards
                a1 = a1 > N ? N : a1;
                rs0 = a0;
                rs1 = a1 < a0 ? a0 : a1;
                float dym = fmaxf(0.0f, fmaxf(y * CELLYZ - p.y,
                                              p.y - (y + 1) * CELLYZ));
                float dzm = fmaxf(0.0f, fmaxf(z * CELLYZ - p.z,
                                              p.z - (z + 1) * CELLYZ));
                rm2f = fmaf(dym, dym, dzm * dzm);
            }
        }
    }

    // ---- Pass 1: packed per-lane 16-bucket histogram of d2 ----
    unsigned long long accLo = 0ull, accHi = 0ull;  // buckets 0-7 / 8-15
    const float skip1 = R2 * 1.0002f;
    #pragma unroll 1
    for (int r = 0; r < 9; r++) {
        float rm2 = __shfl_sync(FULLMASK, rm2f, r);
        if (rm2 > skip1) continue;
        int l0 = __shfl_sync(FULLMASK, rs0, r);
        int l1 = __shfl_sync(FULLMASK, rs1, r);
        for (int c0b = l0; c0b < l1; c0b += 32) {
            int l = c0b + lane;
            if (l < l1) {
                float4 c = pbase[l];
                float dx = c.x - p.x, dy = c.y - p.y, dz = c.z - p.z;
                float d2 = fmaf(dx, dx, fmaf(dy, dy, dz * dz));
                int bk = (int)(d2 * CSCALE);
                if (bk < 16) {
                    unsigned long long bit = 1ull << ((bk & 7) * 8);
                    if (bk < 8) accLo += bit; else accHi += bit;
                }
            }
        }
    }
    // Warp-reduce the two packed histograms (bucket totals <= ~60 < 255).
    #pragma unroll
    for (int o = 16; o; o >>= 1) {
        accLo += __shfl_xor_sync(FULLMASK, accLo, o);
        accHi += __shfl_xor_sync(FULLMASK, accHi, o);
    }
    // Lane k (k<16) extracts bucket k count; 16-lane inclusive prefix.
    unsigned long long selv = (lane < 8) ? accLo : accHi;
    unsigned cntb = (unsigned)((selv >> ((lane & 7) * 8)) & 0xFFull);
    unsigned cum = cntb;
    #pragma unroll
    for (int d = 1; d < 16; d <<= 1) {
        unsigned u = __shfl_up_sync(FULLMASK, cum, d);
        if (lane >= d) cum += u;
    }
    unsigned bal = __ballot_sync(FULLMASK, lane < 16 && cum >= 32u);
    int Bs = 16;                        // 16 => fewer than 32 in radius
    int need = 0;
    if (bal) {
        Bs = __ffs(bal) - 1;
        unsigned cumB = __shfl_sync(FULLMASK, cum, Bs);
        unsigned cntB = __shfl_sync(FULLMASK, cntb, Bs);
        need = 32 - (int)(cumB - cntB);
    }
    float t_hi  = (Bs < 16) ? (float)(Bs + 1) * (R2 / 16.0f) : R2;
    float rp    = sqrtf(t_hi) * 1.0001f;
    float skip2 = t_hi * 1.0002f;

    // ---- Pass 2: accumulate bucket<Bs; select within bucket==Bs ----
    int xl2 = cellx(p.x - rp), xh2 = cellx(p.x + rp);
    int ps0 = 0, ps1 = 0;
    if (lane < 9 && rb >= 0) {
        int a0 = g_off[rb + xl2] - base;
        int a1 = g_off[rb + xh2 + 1] - base;
        a0 = a0 < 0 ? 0 : a0;
        a1 = a1 > N ? N : a1;
        ps0 = a0;
        ps1 = a1 < a0 ? a0 : a1;
    }

    float acc = 0.0f;
    unsigned kk = SENT;                 // sorted list of bucket==Bs keys
    #pragma unroll 1
    for (int r = 0; r < 9; r++) {
        float rm2 = __shfl_sync(FULLMASK, rm2f, r);
        if (rm2 > skip2) continue;
        int l0 = __shfl_sync(FULLMASK, ps0, r);
        int l1 = __shfl_sync(FULLMASK, ps1, r);
        for (int c0b = l0; c0b < l1; c0b += 32) {
            int l = c0b + lane;
            unsigned pk = SENT;
            if (l < l1) {
                float4 c = pbase[l];
                float dx = c.x - p.x, dy = c.y - p.y, dz = c.z - p.z;
                float d2 = fmaf(dx, dx, fmaf(dy, dy, dz * dz));
                int bk = (int)(d2 * CSCALE);
                if (bk < Bs) {                      // definite neighbor
                    float df = p.w - c.w;
                    acc = fmaf(df, df, acc);
                } else if (bk == Bs && Bs < 16) {   // boundary bucket
                    pk = (__float_as_uint(d2) & 0xFFFFF000u) | (unsigned)l;
                }
            }
            unsigned want = __ballot_sync(FULLMASK, pk != SENT);
            while (want) {
                int src = __ffs(want) - 1;
                want &= want - 1;
                unsigned v  = __shfl_sync(FULLMASK, pk, src);
                unsigned pd = __shfl_up_sync(FULLMASK, kk, 1);
                if (lane == 0) pd = 0u;
                if (kk > v) kk = pd > v ? pd : v;   // sorted insert
            }
        }
    }

    // First `need` members of the (ascending) boundary list contribute.
    if (kk != SENT && lane < need) {
        int l = (int)(kk & 0xFFFu);
        float fj = pbase[l].w;
        float df = p.w - fj;
        acc = fmaf(df, df, acc);
    }

    #pragma unroll
    for (int o = 16; o; o >>= 1) acc += __shfl_xor_sync(FULLMASK, acc, o);
    if (lane == 0) swarp[wid] = acc;
    __syncthreads();
    if (threadIdx.x == 0) {
        float s = 0.0f;
        #pragma unroll
        for (int w = 0; w < 8; w++) s += swarp[w];
        g_var[blockIdx.x] = s;
    }

    // ---- last-block deterministic reduction ----
    __threadfence();
    if (threadIdx.x == 0)
        amLast = (atomicAdd(&g_done, 1u) == (unsigned)(NBLK - 1));
    __syncthreads();
    if (amLast) {
        double a = 0.0;
        for (int i = threadIdx.x; i < NBLK; i += 256) a += (double)g_var[i];
        sd[threadIdx.x] = a;
        __syncthreads();
        for (int d = 128; d; d >>= 1) {
            if (threadIdx.x < d) sd[threadIdx.x] += sd[threadIdx.x + d];
            __syncthreads();
        }
        if (threadIdx.x == 0) out[0] = (float)(0.5 * sd[0] / (double)BN);
    }
}

extern "C" void kernel_launch(void* const* d_in, const int* in_sizes, int n_in,
                              void* d_out, int out_size) {
    const float* pos = (const float*)d_in[0];
    const float* f   = (const float*)d_in[1];
    if (n_in >= 2 && in_sizes[0] == BN && in_sizes[1] == 3 * BN) {
        const float* tmp = pos; pos = f; f = tmp;   // defensive input order
    }
    float* out = (float*)d_out;

    k_build<<<B, 1024>>>(pos, f);
    k_main<<<NBLK, 256>>>(out);
}